// round 1
// baseline (speedup 1.0000x reference)
#include <cuda_runtime.h>

#define M_ROWS   524288
#define N_COMBOS 21
#define K_SAMP   1024
#define BOARD    27

// LUTs: index = (int)x_value + 2  (x in {-2..2})
__device__ float2 g_lutA[5];  // (sum_lt, sum_eq) for a = x0 + min_d0
__device__ float2 g_lutB[5];  // (sum_eq, sum_gt) for b = x25 + max_d25

// Dice factors: (d1,d2), d1<=d2, 1/36 if equal else 2/36.
// Diagonal (1/36) at indices 0,6,11,15,18,20.
__constant__ float c_factors[N_COMBOS] = {
    1.0f/36.0f, 2.0f/36.0f, 2.0f/36.0f, 2.0f/36.0f, 2.0f/36.0f, 2.0f/36.0f,
    1.0f/36.0f, 2.0f/36.0f, 2.0f/36.0f, 2.0f/36.0f, 2.0f/36.0f,
    1.0f/36.0f, 2.0f/36.0f, 2.0f/36.0f, 2.0f/36.0f,
    1.0f/36.0f, 2.0f/36.0f, 2.0f/36.0f,
    1.0f/36.0f, 2.0f/36.0f,
    1.0f/36.0f
};

// One block, 21 warps. Warp n reduces combo n's min(deltas[n,:,0]) / max(deltas[n,:,25]),
// then the first 10 threads build the two 5-entry LUTs.
__global__ void __launch_bounds__(N_COMBOS * 32)
precompute_kernel(const float* __restrict__ deltas) {
    const int warp = threadIdx.x >> 5;
    const int lane = threadIdx.x & 31;

    __shared__ float s_min[N_COMBOS];
    __shared__ float s_max[N_COMBOS];

    const float* base = deltas + (size_t)warp * K_SAMP * BOARD;
    float mn =  1e30f;
    float mx = -1e30f;
    #pragma unroll
    for (int k = lane; k < K_SAMP; k += 32) {
        mn = fminf(mn, __ldg(base + (size_t)k * BOARD + 0));
        mx = fmaxf(mx, __ldg(base + (size_t)k * BOARD + 25));
    }
    #pragma unroll
    for (int o = 16; o; o >>= 1) {
        mn = fminf(mn, __shfl_xor_sync(0xffffffffu, mn, o));
        mx = fmaxf(mx, __shfl_xor_sync(0xffffffffu, mx, o));
    }
    if (lane == 0) { s_min[warp] = mn; s_max[warp] = mx; }
    __syncthreads();

    if (threadIdx.x < 10) {
        const int  v   = threadIdx.x % 5;         // value index: x = v - 2
        const bool isB = threadIdx.x >= 5;
        const float xv = (float)(v - 2);
        float s0 = 0.0f, s1 = 0.0f;
        #pragma unroll
        for (int n = 0; n < N_COMBOS; n++) {
            const float f = c_factors[n];
            if (!isB) {
                const float a = xv + s_min[n];
                if (a < -1.0f)       s0 += f;
                else if (a == -1.0f) s1 += f;
            } else {
                const float b = xv + s_max[n];
                if (b == 1.0f)       s0 += f;
                else if (b > 1.0f)   s1 += f;
            }
        }
        if (!isB) g_lutA[v] = make_float2(s0, s1);
        else      g_lutB[v] = make_float2(s0, s1);
    }
}

// Streaming kernel: 1 thread = 1 row. Reads x[m,0] and x[m,25], writes float4 out[m].
__global__ void __launch_bounds__(256)
main_kernel(const float* __restrict__ x, float4* __restrict__ out) {
    const int m = blockIdx.x * blockDim.x + threadIdx.x;
    if (m >= M_ROWS) return;

    const size_t rb = (size_t)m * BOARD;
    const float x0  = __ldg(x + rb + 0);
    const float x25 = __ldg(x + rb + 25);

    // x values are exact small integers; truncation cast is exact.
    const int ia = (int)x0  + 2;
    const int ib = (int)x25 + 2;

    const float2 A = g_lutA[ia];
    const float2 B = g_lutB[ib];

    out[m] = make_float4(A.x, A.y, B.x, B.y);
}

extern "C" void kernel_launch(void* const* d_in, const int* in_sizes, int n_in,
                              void* d_out, int out_size) {
    const float* x      = (const float*)d_in[0];   // [M, 27]
    const float* deltas = (const float*)d_in[1];   // [21, 1024, 27]
    float4* out = (float4*)d_out;                  // [M, 4]

    precompute_kernel<<<1, N_COMBOS * 32>>>(deltas);
    main_kernel<<<M_ROWS / 256, 256>>>(x, out);
}

// round 2
// speedup vs baseline: 1.2992x; 1.2992x over previous
#include <cuda_runtime.h>

#define M_ROWS   524288
#define N_COMBOS 21
#define K_SAMP   1024
#define BOARD    27

// Per-combo reductions + LUTs in device globals.
__device__ float    g_min[N_COMBOS];
__device__ float    g_max[N_COMBOS];
__device__ unsigned g_count = 0;          // last-block-arrives counter (reset each run)
__device__ float2   g_lutA[5];            // (sum_lt, sum_eq) for a = x0 + min_d0
__device__ float2   g_lutB[5];            // (sum_eq, sum_gt) for b = x25 + max_d25

// Dice factors: (d1,d2), d1<=d2, 1/36 if equal else 2/36.
// Diagonal (1/36) at indices 0,6,11,15,18,20.
__constant__ float c_factors[N_COMBOS] = {
    1.0f/36.0f, 2.0f/36.0f, 2.0f/36.0f, 2.0f/36.0f, 2.0f/36.0f, 2.0f/36.0f,
    1.0f/36.0f, 2.0f/36.0f, 2.0f/36.0f, 2.0f/36.0f, 2.0f/36.0f,
    1.0f/36.0f, 2.0f/36.0f, 2.0f/36.0f, 2.0f/36.0f,
    1.0f/36.0f, 2.0f/36.0f, 2.0f/36.0f,
    1.0f/36.0f, 2.0f/36.0f,
    1.0f/36.0f
};

// 21 blocks, 256 threads each. Block n reduces combo n's min(deltas[n,:,0]) and
// max(deltas[n,:,25]). The last block to finish builds the two 5-entry LUTs and
// resets the counter (so each graph replay is identical).
__global__ void __launch_bounds__(256)
precompute_kernel(const float* __restrict__ deltas) {
    const int n    = blockIdx.x;
    const int tid  = threadIdx.x;
    const int lane = tid & 31;
    const int warp = tid >> 5;

    const float* base = deltas + (size_t)n * K_SAMP * BOARD;
    float mn =  1e30f;
    float mx = -1e30f;
    #pragma unroll
    for (int k = tid; k < K_SAMP; k += 256) {
        mn = fminf(mn, __ldg(base + (size_t)k * BOARD + 0));
        mx = fmaxf(mx, __ldg(base + (size_t)k * BOARD + 25));
    }
    #pragma unroll
    for (int o = 16; o; o >>= 1) {
        mn = fminf(mn, __shfl_xor_sync(0xffffffffu, mn, o));
        mx = fmaxf(mx, __shfl_xor_sync(0xffffffffu, mx, o));
    }

    __shared__ float s_mn[8], s_mx[8];
    if (lane == 0) { s_mn[warp] = mn; s_mx[warp] = mx; }
    __syncthreads();

    __shared__ bool s_isLast;
    if (tid == 0) {
        float bmn = s_mn[0], bmx = s_mx[0];
        #pragma unroll
        for (int w = 1; w < 8; w++) {
            bmn = fminf(bmn, s_mn[w]);
            bmx = fmaxf(bmx, s_mx[w]);
        }
        g_min[n] = bmn;
        g_max[n] = bmx;
        __threadfence();                               // publish before counting
        unsigned old = atomicAdd(&g_count, 1u);
        s_isLast = (old == N_COMBOS - 1);
    }
    __syncthreads();

    if (s_isLast) {
        if (tid < 10) {
            const int  v   = tid % 5;                  // x value = v - 2
            const bool isB = tid >= 5;
            const float xv = (float)(v - 2);
            float s0 = 0.0f, s1 = 0.0f;
            #pragma unroll
            for (int c = 0; c < N_COMBOS; c++) {
                const float f = c_factors[c];
                if (!isB) {
                    const float a = xv + *(volatile float*)&g_min[c];
                    if (a < -1.0f)       s0 += f;
                    else if (a == -1.0f) s1 += f;
                } else {
                    const float b = xv + *(volatile float*)&g_max[c];
                    if (b == 1.0f)       s0 += f;
                    else if (b > 1.0f)   s1 += f;
                }
            }
            if (!isB) g_lutA[v] = make_float2(s0, s1);
            else      g_lutB[v] = make_float2(s0, s1);
        }
        if (tid == 0) g_count = 0;                     // reset for next graph replay
    }
}

// Streaming kernel: 2 rows per thread (4 independent loads in flight).
// Scalar loads touch only the needed 32B sectors — optimal when x is L2-resident
// across graph replays (67MB working set < 126MB L2).
__global__ void __launch_bounds__(256)
main_kernel(const float* __restrict__ x, float4* __restrict__ out) {
    const int t  = blockIdx.x * blockDim.x + threadIdx.x;
    const int m0 = t * 2;

    const size_t rb0 = (size_t)m0 * BOARD;
    const size_t rb1 = rb0 + BOARD;
    const float x0a  = __ldg(x + rb0 + 0);
    const float x25a = __ldg(x + rb0 + 25);
    const float x0b  = __ldg(x + rb1 + 0);
    const float x25b = __ldg(x + rb1 + 25);

    // x values are exact small integers in [-2,2]; truncation cast is exact.
    const float2 Aa = g_lutA[(int)x0a  + 2];
    const float2 Ba = g_lutB[(int)x25a + 2];
    const float2 Ab = g_lutA[(int)x0b  + 2];
    const float2 Bb = g_lutB[(int)x25b + 2];

    out[m0 + 0] = make_float4(Aa.x, Aa.y, Ba.x, Ba.y);
    out[m0 + 1] = make_float4(Ab.x, Ab.y, Bb.x, Bb.y);
}

extern "C" void kernel_launch(void* const* d_in, const int* in_sizes, int n_in,
                              void* d_out, int out_size) {
    const float* x      = (const float*)d_in[0];   // [M, 27]
    const float* deltas = (const float*)d_in[1];   // [21, 1024, 27]
    float4* out = (float4*)d_out;                  // [M, 4]

    precompute_kernel<<<N_COMBOS, 256>>>(deltas);
    main_kernel<<<M_ROWS / 512, 256>>>(x, out);
}